// round 1
// baseline (speedup 1.0000x reference)
#include <cuda_runtime.h>
#include <cuda_bf16.h>
#include <cstdint>

#define M_MODELS 3
#define B_IMG    16
#define N_BOX    512
#define K_TOT    (M_MODELS * N_BOX)   // 1536
#define PAD      2048
#define WORDS    24                   // 1536 / 64
#define IOU_THR  0.5f
#define BLK_PER_IMG 6                 // 6 * 256 = 1536 rows

// ------------------- device scratch (no allocation allowed) -------------------
__device__ float              g_sbox  [B_IMG * K_TOT * 4];
__device__ float              g_sscore[B_IMG * K_TOT];
__device__ int                g_slabel[B_IMG * K_TOT];
__device__ float              g_sarea [B_IMG * K_TOT];
__device__ unsigned long long g_mask  [(size_t)B_IMG * K_TOT * WORDS]; // 4.7 MB
__device__ unsigned long long g_rownz [B_IMG * WORDS];

// =============================================================================
// K1: per-image stable sort by (score desc, original flat index asc).
// key = (~float_bits(score) << 32) | idx  -> ascending sort.
// Also gathers sorted boxes / labels / areas into scratch and zeroes rownz.
// =============================================================================
__global__ __launch_bounds__(1024)
void k_sort(const float* __restrict__ boxes, const float* __restrict__ scores,
            const int* __restrict__ labels, const float* __restrict__ weights) {
    __shared__ unsigned long long key[PAD];
    const int b   = blockIdx.x;
    const int tid = threadIdx.x;

    const float w0 = weights[0], w1 = weights[1], w2 = weights[2];

    #pragma unroll
    for (int s = tid; s < PAD; s += 1024) {
        unsigned long long kk = ~0ull;
        if (s < K_TOT) {
            const int m = s >> 9, n = s & (N_BOX - 1);
            const float wm = (m == 0) ? w0 : ((m == 1) ? w1 : w2);
            const float sc = scores[(m * B_IMG + b) * N_BOX + n] * wm;
            kk = ((unsigned long long)(~__float_as_uint(sc)) << 32) | (unsigned)s;
        }
        key[s] = kk;
    }

    // bitonic sort, ascending
    for (unsigned kstage = 2; kstage <= PAD; kstage <<= 1) {
        for (unsigned j = kstage >> 1; j > 0; j >>= 1) {
            __syncthreads();
            const unsigned i = ((tid & ~(j - 1)) << 1) | (tid & (j - 1));
            const unsigned p = i | j;
            const unsigned long long a = key[i];
            const unsigned long long c = key[p];
            const bool up = ((i & kstage) == 0);
            if ((a > c) == up) { key[i] = c; key[p] = a; }
        }
    }
    __syncthreads();

    for (int r = tid; r < K_TOT; r += 1024) {
        const unsigned long long kk = key[r];
        const int   e  = (int)(kk & 0xffffffffu);
        const float sc = __uint_as_float(~(unsigned)(kk >> 32));
        const int m = e >> 9, n = e & (N_BOX - 1);
        const size_t src = ((size_t)m * B_IMG + b) * N_BOX + n;
        const float x1 = boxes[src * 4 + 0];
        const float y1 = boxes[src * 4 + 1];
        const float x2 = boxes[src * 4 + 2];
        const float y2 = boxes[src * 4 + 3];
        const size_t dst = (size_t)b * K_TOT + r;
        g_sbox[dst * 4 + 0] = x1;
        g_sbox[dst * 4 + 1] = y1;
        g_sbox[dst * 4 + 2] = x2;
        g_sbox[dst * 4 + 3] = y2;
        g_sscore[dst] = sc;
        g_slabel[dst] = labels[src];
        g_sarea[dst]  = (x2 - x1) * (y2 - y1);
    }

    if (tid < WORDS) g_rownz[b * WORDS + tid] = 0ull;
}

// =============================================================================
// K2: suppression bitmask. Row i gets bit j (j > i) iff IoU(i,j) > 0.5 and
// labels match. Arithmetic mirrors reference exactly (inter/max(union,1e-9)).
// Grid: B_IMG * BLK_PER_IMG blocks of 256 threads; row i = tid*BLK_PER_IMG+part
// (interleaved for load balance).
// =============================================================================
__global__ __launch_bounds__(256)
void k_mask() {
    __shared__ float4 sb[K_TOT];
    __shared__ float  sa[K_TOT];
    __shared__ int    sl[K_TOT];

    const int img  = blockIdx.x / BLK_PER_IMG;
    const int part = blockIdx.x % BLK_PER_IMG;

    for (int j = threadIdx.x; j < K_TOT; j += 256) {
        const size_t idx = (size_t)img * K_TOT + j;
        sb[j] = *(const float4*)&g_sbox[idx * 4];
        sa[j] = g_sarea[idx];
        sl[j] = g_slabel[idx];
    }
    __syncthreads();

    const int i = threadIdx.x * BLK_PER_IMG + part;     // < K_TOT
    const float4 bi = sb[i];
    const float  ai = sa[i];
    const int    li = sl[i];

    unsigned long long nzany = 0ull;
    for (int w = 0; w < WORDS; w++) {
        unsigned long long mword = 0ull;
        const int j0 = w * 64;
        if (j0 + 63 > i) {
            #pragma unroll 4
            for (int t = 0; t < 64; t++) {
                const int j = j0 + t;
                if (j > i && li == sl[j]) {
                    const float4 bj = sb[j];
                    float iw = fminf(bi.z, bj.z) - fmaxf(bi.x, bj.x);
                    iw = fmaxf(iw, 0.0f);
                    float ih = fminf(bi.w, bj.w) - fmaxf(bi.y, bj.y);
                    ih = fmaxf(ih, 0.0f);
                    const float inter = iw * ih;
                    const float uni   = ai + sa[j] - inter;
                    const float iou   = inter / fmaxf(uni, 1e-9f);
                    if (iou > IOU_THR) mword |= (1ull << t);
                }
            }
        }
        g_mask[((size_t)img * K_TOT + i) * WORDS + w] = mword;
        nzany |= mword;
    }
    if (nzany)
        atomicOr(&g_rownz[img * WORDS + (i >> 6)], 1ull << (i & 63));
}

// =============================================================================
// K3: sequential greedy reduce (sparse, one warp per image) + output epilogue.
// lane l (<24) owns removed word l. Only rows flagged nonzero are visited.
// keep[i] = bit i clear in final removed word.
// =============================================================================
__global__ __launch_bounds__(256)
void k_reduce(float* __restrict__ out) {
    __shared__ unsigned long long keepw[WORDS];
    const int img  = blockIdx.x;
    const int tid  = threadIdx.x;
    const int lane = tid & 31;

    if (tid < 32) {
        unsigned long long removed = 0ull;
        const unsigned long long rnz =
            (lane < WORDS) ? g_rownz[img * WORDS + lane] : 0ull;
        for (int c = 0; c < WORDS; c++) {
            unsigned long long w   = __shfl_sync(0xffffffffu, removed, c);
            unsigned long long act = __shfl_sync(0xffffffffu, rnz, c) & ~w;
            while (act) {
                const int bit = __ffsll((long long)act) - 1;
                act &= act - 1;
                if (!((w >> bit) & 1ull)) {
                    const int i = c * 64 + bit;
                    const unsigned long long rw =
                        (lane < WORDS)
                            ? g_mask[((size_t)img * K_TOT + i) * WORDS + lane]
                            : 0ull;
                    removed |= rw;
                    w |= __shfl_sync(0xffffffffu, rw, c);
                    act &= ~w;
                }
            }
        }
        if (lane < WORDS) keepw[lane] = ~removed;
    }
    __syncthreads();

    for (int r = tid; r < K_TOT; r += 256) {
        const bool kp = (keepw[r >> 6] >> (r & 63)) & 1ull;
        const float f = kp ? 1.0f : 0.0f;
        const size_t s = (size_t)img * K_TOT + r;
        const size_t o = s * 5;
        out[o + 0] = g_sbox[s * 4 + 0] * f;
        out[o + 1] = g_sbox[s * 4 + 1] * f;
        out[o + 2] = g_sbox[s * 4 + 2] * f;
        out[o + 3] = g_sbox[s * 4 + 3] * f;
        out[o + 4] = g_sscore[s] * f;
    }
}

// =============================================================================
extern "C" void kernel_launch(void* const* d_in, const int* in_sizes, int n_in,
                              void* d_out, int out_size) {
    const float* boxes   = (const float*)d_in[0];
    const float* scores  = (const float*)d_in[1];
    const int*   labels  = (const int*)  d_in[2];
    const float* weights = (const float*)d_in[3];
    float*       out     = (float*)d_out;

    k_sort  <<<B_IMG, 1024>>>(boxes, scores, labels, weights);
    k_mask  <<<B_IMG * BLK_PER_IMG, 256>>>();
    k_reduce<<<B_IMG, 256>>>(out);
}

// round 4
// speedup vs baseline: 2.5851x; 2.5851x over previous
#include <cuda_runtime.h>
#include <cuda_bf16.h>
#include <cstdint>

#define M_MODELS 3
#define B_IMG    16
#define N_BOX    512
#define K_TOT    (M_MODELS * N_BOX)   // 1536
#define PAD      2048
#define WORDS    24                   // 1536 / 64
#define IOU_THR  0.5f
#define RBLK_PER_IMG 192              // 192 blocks * 8 warps = 1536 rows

// ------------------- device scratch (no allocation allowed) -------------------
__device__ float              g_sbox  [B_IMG * K_TOT * 4];
__device__ float              g_sscore[B_IMG * K_TOT];
__device__ int                g_slabel[B_IMG * K_TOT];
__device__ float              g_sarea [B_IMG * K_TOT];
__device__ unsigned long long g_mask  [(size_t)B_IMG * K_TOT * WORDS];
__device__ unsigned long long g_rownz [B_IMG * WORDS];

// =============================================================================
// K1: per-image stable sort by (score desc, original flat index asc).
// key = (~float_bits(score) << 32) | idx  -> ascending sort.
// Bitonic. A stage with j<=32 touches only the warp's private 64-elem block.
// A __syncwarp suffices ONLY when BOTH the previous stage (producer) and the
// current stage (consumer) are warp-local; any cross-warp stage on either
// side needs __syncthreads. (R2 checked only consumer, R3 only producer —
// both directions race.)
// =============================================================================
__global__ __launch_bounds__(1024)
void k_sort(const float* __restrict__ boxes, const float* __restrict__ scores,
            const int* __restrict__ labels, const float* __restrict__ weights) {
    __shared__ unsigned long long key[PAD];
    const int b   = blockIdx.x;
    const int tid = threadIdx.x;

    const float w0 = weights[0], w1 = weights[1], w2 = weights[2];

    #pragma unroll
    for (int s = tid; s < PAD; s += 1024) {
        unsigned long long kk = ~0ull;
        if (s < K_TOT) {
            const int m = s >> 9, n = s & (N_BOX - 1);
            const float wm = (m == 0) ? w0 : ((m == 1) ? w1 : w2);
            const float sc = scores[(m * B_IMG + b) * N_BOX + n] * wm;
            kk = ((unsigned long long)(~__float_as_uint(sc)) << 32) | (unsigned)s;
        }
        key[s] = kk;
    }

    // bitonic sort, ascending
    bool prev_cross = true;   // initial load was block-wide
    for (unsigned kstage = 2; kstage <= PAD; kstage <<= 1) {
        for (unsigned j = kstage >> 1; j > 0; j >>= 1) {
            const bool cur_cross = (j > 32);
            if (prev_cross || cur_cross) __syncthreads(); else __syncwarp();
            const unsigned i = ((tid & ~(j - 1)) << 1) | (tid & (j - 1));
            const unsigned p = i | j;
            const unsigned long long a = key[i];
            const unsigned long long c = key[p];
            const bool up = ((i & kstage) == 0);
            if ((a > c) == up) { key[i] = c; key[p] = a; }
            prev_cross = cur_cross;
        }
    }
    __syncthreads();

    for (int r = tid; r < K_TOT; r += 1024) {
        const unsigned long long kk = key[r];
        const int   e  = (int)(kk & 0xffffffffu);
        const float sc = __uint_as_float(~(unsigned)(kk >> 32));
        const int m = e >> 9, n = e & (N_BOX - 1);
        const size_t src = ((size_t)m * B_IMG + b) * N_BOX + n;
        const float x1 = boxes[src * 4 + 0];
        const float y1 = boxes[src * 4 + 1];
        const float x2 = boxes[src * 4 + 2];
        const float y2 = boxes[src * 4 + 3];
        const size_t dst = (size_t)b * K_TOT + r;
        g_sbox[dst * 4 + 0] = x1;
        g_sbox[dst * 4 + 1] = y1;
        g_sbox[dst * 4 + 2] = x2;
        g_sbox[dst * 4 + 3] = y2;
        g_sscore[dst] = sc;
        g_slabel[dst] = labels[src];
        g_sarea[dst]  = (x2 - x1) * (y2 - y1);
    }

    if (tid < WORDS) g_rownz[b * WORDS + tid] = 0ull;
}

// =============================================================================
// K2: suppression bitmask, warp-per-row with ballot.
// Row i gets bit j (j > i) iff IoU(i,j) > 0.5 and labels match.
// Only words w >= i>>6 are written (lower ones are identically zero and are
// never read by k_reduce). Rows interleaved across blocks for load balance.
// =============================================================================
__global__ __launch_bounds__(256)
void k_mask() {
    __shared__ float4 sb[K_TOT];
    __shared__ float  sa[K_TOT];
    __shared__ int    sl[K_TOT];

    const int img  = blockIdx.x / RBLK_PER_IMG;
    const int rblk = blockIdx.x % RBLK_PER_IMG;

    for (int j = threadIdx.x; j < K_TOT; j += 256) {
        const size_t idx = (size_t)img * K_TOT + j;
        sb[j] = *(const float4*)&g_sbox[idx * 4];
        sa[j] = g_sarea[idx];
        sl[j] = g_slabel[idx];
    }
    __syncthreads();

    const int warp = threadIdx.x >> 5;
    const int lane = threadIdx.x & 31;
    const int i    = warp * RBLK_PER_IMG + rblk;     // row, balanced across blocks

    const float4 bi = sb[i];
    const float  ai = sa[i];
    const int    li = sl[i];
    const int    w0 = i >> 6;

    unsigned long long nz = 0ull;
    for (int w = w0; w < WORDS; w++) {
        const int jlo = w * 64 + lane;
        const int jhi = jlo + 32;

        bool p0 = false, p1 = false;
        {
            const int j = jlo;
            if (j > i && li == sl[j]) {
                const float4 bj = sb[j];
                float iw = fmaxf(fminf(bi.z, bj.z) - fmaxf(bi.x, bj.x), 0.0f);
                float ih = fmaxf(fminf(bi.w, bj.w) - fmaxf(bi.y, bj.y), 0.0f);
                const float inter = iw * ih;
                const float uni   = ai + sa[j] - inter;
                p0 = (inter / fmaxf(uni, 1e-9f)) > IOU_THR;
            }
        }
        {
            const int j = jhi;
            if (j > i && li == sl[j]) {
                const float4 bj = sb[j];
                float iw = fmaxf(fminf(bi.z, bj.z) - fmaxf(bi.x, bj.x), 0.0f);
                float ih = fmaxf(fminf(bi.w, bj.w) - fmaxf(bi.y, bj.y), 0.0f);
                const float inter = iw * ih;
                const float uni   = ai + sa[j] - inter;
                p1 = (inter / fmaxf(uni, 1e-9f)) > IOU_THR;
            }
        }
        const unsigned lo = __ballot_sync(0xffffffffu, p0);
        const unsigned hi = __ballot_sync(0xffffffffu, p1);
        const unsigned long long mword = ((unsigned long long)hi << 32) | lo;
        if (lane == 0)
            g_mask[((size_t)img * K_TOT + i) * WORDS + w] = mword;
        nz |= mword;
    }
    if (lane == 0 && nz)
        atomicOr(&g_rownz[img * WORDS + w0], 1ull << (i & 63));
}

// =============================================================================
// K3: sequential greedy reduce (sparse, one warp per image) + output epilogue.
// lane l (<24) owns removed word l. Only rows flagged nonzero are visited.
// For a seed row i in chunk c, mask words < c are never loaded (all zero,
// and also never written by k_mask).
// =============================================================================
__global__ __launch_bounds__(256)
void k_reduce(float* __restrict__ out) {
    __shared__ unsigned long long keepw[WORDS];
    const int img  = blockIdx.x;
    const int tid  = threadIdx.x;
    const int lane = tid & 31;

    if (tid < 32) {
        unsigned long long removed = 0ull;
        const unsigned long long rnz =
            (lane < WORDS) ? g_rownz[img * WORDS + lane] : 0ull;
        for (int c = 0; c < WORDS; c++) {
            unsigned long long w   = __shfl_sync(0xffffffffu, removed, c);
            unsigned long long act = __shfl_sync(0xffffffffu, rnz, c) & ~w;
            while (act) {
                const int bit = __ffsll((long long)act) - 1;
                act &= act - 1;
                if (!((w >> bit) & 1ull)) {
                    const int i = c * 64 + bit;
                    const unsigned long long rw =
                        (lane >= c && lane < WORDS)
                            ? g_mask[((size_t)img * K_TOT + i) * WORDS + lane]
                            : 0ull;
                    removed |= rw;
                    w |= __shfl_sync(0xffffffffu, rw, c);
                    act &= ~w;
                }
            }
        }
        if (lane < WORDS) keepw[lane] = ~removed;
    }
    __syncthreads();

    for (int r = tid; r < K_TOT; r += 256) {
        const bool kp = (keepw[r >> 6] >> (r & 63)) & 1ull;
        const float f = kp ? 1.0f : 0.0f;
        const size_t s = (size_t)img * K_TOT + r;
        const size_t o = s * 5;
        out[o + 0] = g_sbox[s * 4 + 0] * f;
        out[o + 1] = g_sbox[s * 4 + 1] * f;
        out[o + 2] = g_sbox[s * 4 + 2] * f;
        out[o + 3] = g_sbox[s * 4 + 3] * f;
        out[o + 4] = g_sscore[s] * f;
    }
}

// =============================================================================
extern "C" void kernel_launch(void* const* d_in, const int* in_sizes, int n_in,
                              void* d_out, int out_size) {
    const float* boxes   = (const float*)d_in[0];
    const float* scores  = (const float*)d_in[1];
    const int*   labels  = (const int*)  d_in[2];
    const float* weights = (const float*)d_in[3];
    float*       out     = (float*)d_out;

    k_sort  <<<B_IMG, 1024>>>(boxes, scores, labels, weights);
    k_mask  <<<B_IMG * RBLK_PER_IMG, 256>>>();
    k_reduce<<<B_IMG, 256>>>(out);
}

// round 5
// speedup vs baseline: 4.0846x; 1.5800x over previous
#include <cuda_runtime.h>
#include <cuda_bf16.h>
#include <cstdint>

typedef unsigned long long ull;

#define M_MODELS 3
#define B_IMG    16
#define N_BOX    512
#define K_TOT    (M_MODELS * N_BOX)   // 1536
#define PAD      2048
#define WORDS    24                   // 1536 / 64
#define IOU_THR  0.5f
#define MASK_RB  48                   // blocks per image in k_mask (4 rows/warp)
#define SEED_CAP 224                  // seed rows prefetched to smem in k_reduce

// ------------------- device scratch (no allocation allowed) -------------------
__device__ float g_sbox  [B_IMG * K_TOT * 4];
__device__ float g_sscore[B_IMG * K_TOT];
__device__ int   g_slabel[B_IMG * K_TOT];
__device__ float g_sarea [B_IMG * K_TOT];
__device__ ull   g_mask  [(size_t)B_IMG * K_TOT * WORDS];
__device__ ull   g_rownz [B_IMG * WORDS];

__device__ __forceinline__ void cswap(ull& x, ull& y, bool up) {
    if ((x > y) == up) { ull t = x; x = y; y = t; }
}

// one bitonic stage with j<=16 via shfl.bfly; v is the key of element e
__device__ __forceinline__ ull shfl_stage(ull v, int e, unsigned j, unsigned ks) {
    const ull  o     = __shfl_xor_sync(0xffffffffu, v, j);
    const bool up    = ((e & ks) == 0);
    const bool lower = ((e & j) == 0);
    return ((v < o) == (lower == up)) ? v : o;
}

// =============================================================================
// K1: per-image stable sort by (score desc, original flat index asc).
// key = (~float_bits(score) << 32) | idx  -> ascending sort.
// Hybrid bitonic: each thread holds 2 keys (elements eA=64w+l, eB=eA+32).
// kstage 2..64 entirely in registers (warp-local 64-elem blocks, shfl.bfly).
// kstage 128..2048: only stages j>=64 go through smem (+barrier); the j<=32
// tail of each kstage again runs in registers. 15 smem stages total.
// =============================================================================
__global__ __launch_bounds__(1024)
void k_sort(const float* __restrict__ boxes, const float* __restrict__ scores,
            const int* __restrict__ labels, const float* __restrict__ weights) {
    __shared__ ull key[PAD];
    const int b   = blockIdx.x;
    const int tid = threadIdx.x;
    const int w   = tid >> 5, l = tid & 31;
    const int eA  = (w << 6) | l;
    const int eB  = eA | 32;

    const float w0 = weights[0], w1 = weights[1], w2 = weights[2];

    auto mkkey = [&](int s) -> ull {
        if (s >= K_TOT) return ~0ull;
        const int m = s >> 9, n = s & (N_BOX - 1);
        const float wm = (m == 0) ? w0 : ((m == 1) ? w1 : w2);
        const float sc = scores[(m * B_IMG + b) * N_BOX + n] * wm;
        return ((ull)(~__float_as_uint(sc)) << 32) | (unsigned)s;
    };
    ull a = mkkey(eA);
    ull c = mkkey(eB);

    // ---- phase 1: kstage 2..64 fully in registers ----
    #pragma unroll
    for (int kb = 1; kb <= 6; kb++) {
        const unsigned ks = 1u << kb;
        if (ks == 64) cswap(a, c, ((eA & 64) == 0));      // j=32, in-thread
        const unsigned jstart = (ks == 64) ? 16u : (ks >> 1);
        #pragma unroll
        for (unsigned j = jstart; j >= 1; j >>= 1) {
            a = shfl_stage(a, eA, j, ks);
            c = shfl_stage(c, eB, j, ks);
        }
    }
    key[eA] = a;
    key[eB] = c;

    // ---- phase 2: kstage 128..2048 ----
    #pragma unroll
    for (unsigned ks = 128; ks <= PAD; ks <<= 1) {
        for (unsigned j = ks >> 1; j >= 64; j >>= 1) {
            __syncthreads();
            const unsigned i = ((tid & ~(j - 1)) << 1) | (tid & (j - 1));
            const unsigned p = i | j;
            const ull x = key[i];
            const ull y = key[p];
            const bool up = ((i & ks) == 0);
            if ((x > y) == up) { key[i] = y; key[p] = x; }
        }
        __syncthreads();
        a = key[eA]; c = key[eB];
        cswap(a, c, ((eA & ks) == 0));                    // j=32
        #pragma unroll
        for (unsigned j = 16; j >= 1; j >>= 1) {
            a = shfl_stage(a, eA, j, ks);
            c = shfl_stage(c, eB, j, ks);
        }
        key[eA] = a; key[eB] = c;
    }
    __syncthreads();

    for (int r = tid; r < K_TOT; r += 1024) {
        const ull kk = key[r];
        const int   e  = (int)(kk & 0xffffffffu);
        const float sc = __uint_as_float(~(unsigned)(kk >> 32));
        const int m = e >> 9, n = e & (N_BOX - 1);
        const size_t src = ((size_t)m * B_IMG + b) * N_BOX + n;
        const float x1 = boxes[src * 4 + 0];
        const float y1 = boxes[src * 4 + 1];
        const float x2 = boxes[src * 4 + 2];
        const float y2 = boxes[src * 4 + 3];
        const size_t dst = (size_t)b * K_TOT + r;
        g_sbox[dst * 4 + 0] = x1;
        g_sbox[dst * 4 + 1] = y1;
        g_sbox[dst * 4 + 2] = x2;
        g_sbox[dst * 4 + 3] = y2;
        g_sscore[dst] = sc;
        g_slabel[dst] = labels[src];
        g_sarea[dst]  = (x2 - x1) * (y2 - y1);
    }

    if (tid < WORDS) g_rownz[b * WORDS + tid] = 0ull;
}

// =============================================================================
// K2: suppression bitmask, warp-per-row with ballot; 4 rows per warp so the
// per-CTA smem table fill is amortized 4x (L2 traffic 113MB -> 28MB).
// Row i gets bit j (j > i) iff IoU(i,j) > 0.5 and labels match.
// Only words w >= i>>6 are written (lower ones are identically zero and are
// never written nor meaningfully read).
// =============================================================================
__global__ __launch_bounds__(256)
void k_mask() {
    __shared__ float4 sb[K_TOT];
    __shared__ float  sa[K_TOT];
    __shared__ int    sl[K_TOT];

    const int img  = blockIdx.x / MASK_RB;
    const int rblk = blockIdx.x % MASK_RB;

    for (int j = threadIdx.x; j < K_TOT; j += 256) {
        const size_t idx = (size_t)img * K_TOT + j;
        sb[j] = *(const float4*)&g_sbox[idx * 4];
        sa[j] = g_sarea[idx];
        sl[j] = g_slabel[idx];
    }
    __syncthreads();

    const int warp = threadIdx.x >> 5;
    const int lane = threadIdx.x & 31;

    #pragma unroll
    for (int r = 0; r < 4; r++) {
        const int i = (r * 8 + warp) * MASK_RB + rblk;   // rows balanced

        const float4 bi = sb[i];
        const float  ai = sa[i];
        const int    li = sl[i];
        const int    w0 = i >> 6;

        ull nz = 0ull;
        for (int w = w0; w < WORDS; w++) {
            const int jlo = w * 64 + lane;
            const int jhi = jlo + 32;

            bool p0 = false, p1 = false;
            {
                const int j = jlo;
                if (j > i && li == sl[j]) {
                    const float4 bj = sb[j];
                    float iw = fmaxf(fminf(bi.z, bj.z) - fmaxf(bi.x, bj.x), 0.0f);
                    float ih = fmaxf(fminf(bi.w, bj.w) - fmaxf(bi.y, bj.y), 0.0f);
                    const float inter = iw * ih;
                    const float uni   = ai + sa[j] - inter;
                    p0 = (inter / fmaxf(uni, 1e-9f)) > IOU_THR;
                }
            }
            {
                const int j = jhi;
                if (j > i && li == sl[j]) {
                    const float4 bj = sb[j];
                    float iw = fmaxf(fminf(bi.z, bj.z) - fmaxf(bi.x, bj.x), 0.0f);
                    float ih = fmaxf(fminf(bi.w, bj.w) - fmaxf(bi.y, bj.y), 0.0f);
                    const float inter = iw * ih;
                    const float uni   = ai + sa[j] - inter;
                    p1 = (inter / fmaxf(uni, 1e-9f)) > IOU_THR;
                }
            }
            const unsigned lo = __ballot_sync(0xffffffffu, p0);
            const unsigned hi = __ballot_sync(0xffffffffu, p1);
            const ull mword = ((ull)hi << 32) | lo;
            if (lane == 0)
                g_mask[((size_t)img * K_TOT + i) * WORDS + w] = mword;
            nz |= mword;
        }
        if (lane == 0 && nz)
            atomicOr(&g_rownz[img * WORDS + w0], 1ull << (i & 63));
    }
}

// =============================================================================
// K3: greedy reduce. Seed rows (those with any suppression bit) are enumerated,
// their mask rows PREFETCHED into smem in parallel, then one warp runs the
// inherently serial greedy chain entirely from smem (29cyc LDS instead of
// ~600cyc dependent global loads). Epilogue writes (box*keep, score*keep).
// =============================================================================
__global__ __launch_bounds__(256)
void k_reduce(float* __restrict__ out) {
    __shared__ ull   smask[SEED_CAP * WORDS];   // 43008 B
    __shared__ short seeds[K_TOT];              // 3072 B
    __shared__ ull   rnz_s[WORDS];
    __shared__ ull   keepw[WORDS];
    __shared__ int   nseeds_s;

    const int img  = blockIdx.x;
    const int tid  = threadIdx.x;
    const int lane = tid & 31;

    if (tid < WORDS) rnz_s[tid] = g_rownz[img * WORDS + tid];
    __syncthreads();

    if (tid == 0) {
        int n = 0;
        for (int c = 0; c < WORDS; c++) {
            ull v = rnz_s[c];
            while (v) {
                const int bit = __ffsll((long long)v) - 1;
                v &= v - 1;
                seeds[n++] = (short)(c * 64 + bit);
            }
        }
        nseeds_s = n;
    }
    __syncthreads();

    const int ns   = nseeds_s;
    const int npre = ns < SEED_CAP ? ns : SEED_CAP;
    for (int idx = tid; idx < npre * WORDS; idx += 256) {
        const int s  = idx / WORDS;
        const int ww = idx - s * WORDS;
        smask[idx] = g_mask[((size_t)img * K_TOT + (int)seeds[s]) * WORDS + ww];
    }
    __syncthreads();

    if (tid < 32) {
        ull removed = 0ull;
        for (int s = 0; s < ns; s++) {
            const int i = seeds[s];
            const int c = i >> 6;
            const ull wc = __shfl_sync(0xffffffffu, removed, c);
            if (!((wc >> (i & 63)) & 1ull)) {
                ull rw = 0ull;
                if (lane < WORDS)
                    rw = (s < SEED_CAP)
                         ? smask[s * WORDS + lane]
                         : g_mask[((size_t)img * K_TOT + i) * WORDS + lane];
                removed |= rw;
            }
        }
        if (lane < WORDS) keepw[lane] = ~removed;
    }
    __syncthreads();

    for (int r = tid; r < K_TOT; r += 256) {
        const bool kp = (keepw[r >> 6] >> (r & 63)) & 1ull;
        const float f = kp ? 1.0f : 0.0f;
        const size_t s = (size_t)img * K_TOT + r;
        const size_t o = s * 5;
        out[o + 0] = g_sbox[s * 4 + 0] * f;
        out[o + 1] = g_sbox[s * 4 + 1] * f;
        out[o + 2] = g_sbox[s * 4 + 2] * f;
        out[o + 3] = g_sbox[s * 4 + 3] * f;
        out[o + 4] = g_sscore[s] * f;
    }
}

// =============================================================================
extern "C" void kernel_launch(void* const* d_in, const int* in_sizes, int n_in,
                              void* d_out, int out_size) {
    const float* boxes   = (const float*)d_in[0];
    const float* scores  = (const float*)d_in[1];
    const int*   labels  = (const int*)  d_in[2];
    const float* weights = (const float*)d_in[3];
    float*       out     = (float*)d_out;

    k_sort  <<<B_IMG, 1024>>>(boxes, scores, labels, weights);
    k_mask  <<<B_IMG * MASK_RB, 256>>>();
    k_reduce<<<B_IMG, 256>>>(out);
}

// round 6
// speedup vs baseline: 6.1145x; 1.4970x over previous
#include <cuda_runtime.h>
#include <cuda_bf16.h>
#include <cstdint>

typedef unsigned long long ull;

#define M_MODELS 3
#define B_IMG    16
#define N_BOX    512
#define K_TOT    (M_MODELS * N_BOX)   // 1536
#define PAD      2048
#define WORDS    24                   // 1536 / 64
#define MASK_RB  48                   // blocks per image in k_mask (4 rows/warp)
#define SEED_CAP 192                  // seed rows prefetched to smem in reduce

// ------------------- device scratch (no allocation allowed) -------------------
__device__ float g_sbox  [B_IMG * K_TOT * 4];
__device__ float g_sscore[B_IMG * K_TOT];
__device__ int   g_slabel[B_IMG * K_TOT];
__device__ float g_sarea [B_IMG * K_TOT];
__device__ ull   g_mask  [(size_t)B_IMG * K_TOT * WORDS];
__device__ ull   g_rownz [B_IMG * WORDS];
__device__ int   g_done  [B_IMG];

__device__ __forceinline__ void cswap(ull& x, ull& y, bool up) {
    if ((x > y) == up) { ull t = x; x = y; y = t; }
}

// one bitonic stage with j<=16 via shfl.bfly; v is the key of element e
__device__ __forceinline__ ull shfl_stage(ull v, int e, unsigned j, unsigned ks) {
    const ull  o     = __shfl_xor_sync(0xffffffffu, v, j);
    const bool up    = ((e & ks) == 0);
    const bool lower = ((e & j) == 0);
    return ((v < o) == (lower == up)) ? v : o;
}

// =============================================================================
// K1: per-image stable sort by (score desc, original flat index asc).
// key = (~float_bits(score) << 32) | idx  -> ascending sort.
// Hybrid bitonic: kstage 2..64 in registers (shfl), kstage >=128 does j>=64
// stages via smem (15 barriers) and the j<=32 tail in registers.
// Also resets per-image done counter + rownz for the fused mask/reduce pass.
// =============================================================================
__global__ __launch_bounds__(1024)
void k_sort(const float* __restrict__ boxes, const float* __restrict__ scores,
            const int* __restrict__ labels, const float* __restrict__ weights) {
    __shared__ ull key[PAD];
    const int b   = blockIdx.x;
    const int tid = threadIdx.x;
    const int w   = tid >> 5, l = tid & 31;
    const int eA  = (w << 6) | l;
    const int eB  = eA | 32;

    const float w0 = weights[0], w1 = weights[1], w2 = weights[2];

    auto mkkey = [&](int s) -> ull {
        if (s >= K_TOT) return ~0ull;
        const int m = s >> 9, n = s & (N_BOX - 1);
        const float wm = (m == 0) ? w0 : ((m == 1) ? w1 : w2);
        const float sc = scores[(m * B_IMG + b) * N_BOX + n] * wm;
        return ((ull)(~__float_as_uint(sc)) << 32) | (unsigned)s;
    };
    ull a = mkkey(eA);
    ull c = mkkey(eB);

    // ---- phase 1: kstage 2..64 fully in registers ----
    #pragma unroll
    for (int kb = 1; kb <= 6; kb++) {
        const unsigned ks = 1u << kb;
        if (ks == 64) cswap(a, c, ((eA & 64) == 0));      // j=32, in-thread
        const unsigned jstart = (ks == 64) ? 16u : (ks >> 1);
        #pragma unroll
        for (unsigned j = jstart; j >= 1; j >>= 1) {
            a = shfl_stage(a, eA, j, ks);
            c = shfl_stage(c, eB, j, ks);
        }
    }
    key[eA] = a;
    key[eB] = c;

    // ---- phase 2: kstage 128..2048 ----
    #pragma unroll
    for (unsigned ks = 128; ks <= PAD; ks <<= 1) {
        for (unsigned j = ks >> 1; j >= 64; j >>= 1) {
            __syncthreads();
            const unsigned i = ((tid & ~(j - 1)) << 1) | (tid & (j - 1));
            const unsigned p = i | j;
            const ull x = key[i];
            const ull y = key[p];
            const bool up = ((i & ks) == 0);
            if ((x > y) == up) { key[i] = y; key[p] = x; }
        }
        __syncthreads();
        a = key[eA]; c = key[eB];
        cswap(a, c, ((eA & ks) == 0));                    // j=32
        #pragma unroll
        for (unsigned j = 16; j >= 1; j >>= 1) {
            a = shfl_stage(a, eA, j, ks);
            c = shfl_stage(c, eB, j, ks);
        }
        key[eA] = a; key[eB] = c;
    }
    __syncthreads();

    for (int r = tid; r < K_TOT; r += 1024) {
        const ull kk = key[r];
        const int   e  = (int)(kk & 0xffffffffu);
        const float sc = __uint_as_float(~(unsigned)(kk >> 32));
        const int m = e >> 9, n = e & (N_BOX - 1);
        const size_t src = ((size_t)m * B_IMG + b) * N_BOX + n;
        const float x1 = boxes[src * 4 + 0];
        const float y1 = boxes[src * 4 + 1];
        const float x2 = boxes[src * 4 + 2];
        const float y2 = boxes[src * 4 + 3];
        const size_t dst = (size_t)b * K_TOT + r;
        g_sbox[dst * 4 + 0] = x1;
        g_sbox[dst * 4 + 1] = y1;
        g_sbox[dst * 4 + 2] = x2;
        g_sbox[dst * 4 + 3] = y2;
        g_sscore[dst] = sc;
        g_slabel[dst] = labels[src];
        g_sarea[dst]  = (x2 - x1) * (y2 - y1);
    }

    if (tid < WORDS) g_rownz[b * WORDS + tid] = 0ull;
    if (tid == 32)   g_done[b] = 0;
}

// =============================================================================
// K2 (fused): suppression bitmask + (in the image's last-finishing block)
// the greedy reduce and output epilogue.
// Predicate is division-free: iou > 0.5 <=> inter > 0.5*max(union,1e-9);
// 0.5*d is exact in fp32, so this is the exact real comparison.
// =============================================================================
__global__ __launch_bounds__(256)
void k_mask(float* __restrict__ out) {
    __shared__ union Sh {
        struct { float4 sb[K_TOT]; float2 sal[K_TOT]; } m;          // 36.9 KB
        struct { ull smask[SEED_CAP * WORDS]; short seeds[K_TOT];
                 ull rnz[WORDS]; ull keepw[WORDS]; } r;             // 40.3 KB
    } sh;
    __shared__ int s_last, s_ns;

    const int img  = blockIdx.x / MASK_RB;
    const int rblk = blockIdx.x % MASK_RB;
    const int tid  = threadIdx.x;
    const int warp = tid >> 5;
    const int lane = tid & 31;

    // ---- load per-image sorted table ----
    for (int j = tid; j < K_TOT; j += 256) {
        const size_t idx = (size_t)img * K_TOT + j;
        sh.m.sb[j]  = *(const float4*)&g_sbox[idx * 4];
        sh.m.sal[j] = make_float2(g_sarea[idx], __int_as_float(g_slabel[idx]));
    }
    __syncthreads();

    // ---- mask phase: 4 rows per warp, ballot per 32 ----
    #pragma unroll
    for (int r = 0; r < 4; r++) {
        const int i = (r * 8 + warp) * MASK_RB + rblk;

        const float4 bi = sh.m.sb[i];
        const float2 si = sh.m.sal[i];
        const float  ai = si.x;
        const int    li = __float_as_int(si.y);
        const int    w0 = i >> 6;

        ull nz = 0ull;
        for (int w = w0; w < WORDS; w++) {
            const int jlo = w * 64 + lane;
            const int jhi = jlo + 32;

            bool p0 = false, p1 = false;
            {
                const int j = jlo;
                const float2 sj = sh.m.sal[j];
                if (j > i && li == __float_as_int(sj.y)) {
                    const float4 bj = sh.m.sb[j];
                    const float iw = fmaxf(fminf(bi.z, bj.z) - fmaxf(bi.x, bj.x), 0.0f);
                    const float ih = fmaxf(fminf(bi.w, bj.w) - fmaxf(bi.y, bj.y), 0.0f);
                    const float inter = iw * ih;
                    const float uni   = ai + sj.x - inter;
                    p0 = inter > 0.5f * fmaxf(uni, 1e-9f);
                }
            }
            {
                const int j = jhi;
                const float2 sj = sh.m.sal[j];
                if (j > i && li == __float_as_int(sj.y)) {
                    const float4 bj = sh.m.sb[j];
                    const float iw = fmaxf(fminf(bi.z, bj.z) - fmaxf(bi.x, bj.x), 0.0f);
                    const float ih = fmaxf(fminf(bi.w, bj.w) - fmaxf(bi.y, bj.y), 0.0f);
                    const float inter = iw * ih;
                    const float uni   = ai + sj.x - inter;
                    p1 = inter > 0.5f * fmaxf(uni, 1e-9f);
                }
            }
            const unsigned lo = __ballot_sync(0xffffffffu, p0);
            const unsigned hi = __ballot_sync(0xffffffffu, p1);
            const ull mword = ((ull)hi << 32) | lo;
            if (lane == 0)
                g_mask[((size_t)img * K_TOT + i) * WORDS + w] = mword;
            nz |= mword;
        }
        if (lane == 0 && nz)
            atomicOr(&g_rownz[img * WORDS + w0], 1ull << (i & 63));
    }

    // ---- last-block election ----
    __syncthreads();
    if (tid == 0) {
        __threadfence();
        const int old = atomicAdd(&g_done[img], 1);
        s_last = (old == MASK_RB - 1);
    }
    __syncthreads();
    if (!s_last) return;
    __threadfence();   // ensure we see all blocks' g_mask / g_rownz writes

    // ---- reduce phase (smem repurposed) ----
    if (tid < WORDS) sh.r.rnz[tid] = g_rownz[img * WORDS + tid];
    __syncthreads();

    if (tid == 0) {
        int n = 0;
        for (int c = 0; c < WORDS; c++) {
            ull v = sh.r.rnz[c];
            while (v) {
                const int bit = __ffsll((long long)v) - 1;
                v &= v - 1;
                sh.r.seeds[n++] = (short)(c * 64 + bit);
            }
        }
        s_ns = n;
    }
    __syncthreads();

    const int ns   = s_ns;
    const int npre = ns < SEED_CAP ? ns : SEED_CAP;
    for (int idx = tid; idx < npre * WORDS; idx += 256) {
        const int s  = idx / WORDS;
        const int ww = idx - s * WORDS;
        sh.r.smask[idx] =
            g_mask[((size_t)img * K_TOT + (int)sh.r.seeds[s]) * WORDS + ww];
    }
    __syncthreads();

    if (tid < 32) {
        ull removed = 0ull;
        for (int s = 0; s < ns; s++) {
            const int i = sh.r.seeds[s];
            const int c = i >> 6;
            const ull wc = __shfl_sync(0xffffffffu, removed, c);
            if (!((wc >> (i & 63)) & 1ull)) {
                ull rw = 0ull;
                if (lane < WORDS)
                    rw = (s < SEED_CAP)
                         ? sh.r.smask[s * WORDS + lane]
                         : g_mask[((size_t)img * K_TOT + i) * WORDS + lane];
                removed |= rw;
            }
        }
        if (lane < WORDS) sh.r.keepw[lane] = ~removed;
    }
    __syncthreads();

    // ---- epilogue ----
    for (int r = tid; r < K_TOT; r += 256) {
        const bool kp = (sh.r.keepw[r >> 6] >> (r & 63)) & 1ull;
        const float f = kp ? 1.0f : 0.0f;
        const size_t s = (size_t)img * K_TOT + r;
        const size_t o = s * 5;
        out[o + 0] = g_sbox[s * 4 + 0] * f;
        out[o + 1] = g_sbox[s * 4 + 1] * f;
        out[o + 2] = g_sbox[s * 4 + 2] * f;
        out[o + 3] = g_sbox[s * 4 + 3] * f;
        out[o + 4] = g_sscore[s] * f;
    }
}

// =============================================================================
extern "C" void kernel_launch(void* const* d_in, const int* in_sizes, int n_in,
                              void* d_out, int out_size) {
    const float* boxes   = (const float*)d_in[0];
    const float* scores  = (const float*)d_in[1];
    const int*   labels  = (const int*)  d_in[2];
    const float* weights = (const float*)d_in[3];
    float*       out     = (float*)d_out;

    k_sort<<<B_IMG, 1024>>>(boxes, scores, labels, weights);
    k_mask<<<B_IMG * MASK_RB, 256>>>(out);
}

// round 7
// speedup vs baseline: 9.3583x; 1.5305x over previous
#include <cuda_runtime.h>
#include <cuda_bf16.h>
#include <cstdint>

typedef unsigned long long ull;

#define M_MODELS 3
#define B_IMG    16
#define N_BOX    512
#define K_TOT    (M_MODELS * N_BOX)   // 1536
#define PAD      2048
#define NUM_CLS  12
#define CAP      256                  // fast-path bucket capacity
#define W_MAX    4                    // CAP/64 mask words per row

// ------------------- device scratch (no allocation allowed) -------------------
__device__ float g_sbox  [B_IMG * K_TOT * 4];   // sorted boxes
__device__ float g_sscore[B_IMG * K_TOT];       // sorted weighted scores
__device__ int   g_bidx  [B_IMG * K_TOT];       // per-class index lists (ranks)
__device__ int   g_boff  [B_IMG * NUM_CLS];
__device__ int   g_bcnt  [B_IMG * NUM_CLS];

__device__ __forceinline__ void cswap(ull& x, ull& y, bool up) {
    if ((x > y) == up) { ull t = x; x = y; y = t; }
}

// one bitonic stage with j<=16 via shfl.bfly; v is the key of element e
__device__ __forceinline__ ull shfl_stage(ull v, int e, unsigned j, unsigned ks) {
    const ull  o     = __shfl_xor_sync(0xffffffffu, v, j);
    const bool up    = ((e & ks) == 0);
    const bool lower = ((e & j) == 0);
    return ((v < o) == (lower == up)) ? v : o;
}

// division-free exact IoU>0.5 test: 0.5*d is exact in fp32
__device__ __forceinline__ bool iou_gt(const float4 bi, const float ai,
                                       const float4 bj, const float aj) {
    const float iw = fmaxf(fminf(bi.z, bj.z) - fmaxf(bi.x, bj.x), 0.0f);
    const float ih = fmaxf(fminf(bi.w, bj.w) - fmaxf(bi.y, bj.y), 0.0f);
    const float inter = iw * ih;
    const float uni   = ai + aj - inter;
    return inter > 0.5f * fmaxf(uni, 1e-9f);
}

// =============================================================================
// K1: per-image stable sort by (score desc, original flat index asc), then
// stable ballot-compaction of sorted ranks into NUM_CLS per-class buckets.
// key = (~float_bits(score) << 32) | idx  -> ascending sort.
// =============================================================================
__global__ __launch_bounds__(1024)
void k_sort(const float* __restrict__ boxes, const float* __restrict__ scores,
            const int* __restrict__ labels, const float* __restrict__ weights) {
    __shared__ ull   key[PAD];                 // 16 KB
    __shared__ short slab[K_TOT];              // 3 KB (sorted labels)
    __shared__ int   scount[NUM_CLS], soff[NUM_CLS];

    const int b    = blockIdx.x;
    const int tid  = threadIdx.x;
    const int warp = tid >> 5, lane = tid & 31;
    const int eA   = (warp << 6) | lane;
    const int eB   = eA | 32;

    const float w0 = weights[0], w1 = weights[1], w2 = weights[2];

    auto mkkey = [&](int s) -> ull {
        if (s >= K_TOT) return ~0ull;
        const int m = s >> 9, n = s & (N_BOX - 1);
        const float wm = (m == 0) ? w0 : ((m == 1) ? w1 : w2);
        const float sc = scores[(m * B_IMG + b) * N_BOX + n] * wm;
        return ((ull)(~__float_as_uint(sc)) << 32) | (unsigned)s;
    };
    ull a = mkkey(eA);
    ull c = mkkey(eB);

    // ---- kstage 2..64 fully in registers ----
    #pragma unroll
    for (int kb = 1; kb <= 6; kb++) {
        const unsigned ks = 1u << kb;
        if (ks == 64) cswap(a, c, ((eA & 64) == 0));
        const unsigned jstart = (ks == 64) ? 16u : (ks >> 1);
        #pragma unroll
        for (unsigned j = jstart; j >= 1; j >>= 1) {
            a = shfl_stage(a, eA, j, ks);
            c = shfl_stage(c, eB, j, ks);
        }
    }
    key[eA] = a;
    key[eB] = c;

    // ---- kstage 128..2048 ----
    #pragma unroll
    for (unsigned ks = 128; ks <= PAD; ks <<= 1) {
        for (unsigned j = ks >> 1; j >= 64; j >>= 1) {
            __syncthreads();
            const unsigned i = ((tid & ~(j - 1)) << 1) | (tid & (j - 1));
            const unsigned p = i | j;
            const ull x = key[i];
            const ull y = key[p];
            const bool up = ((i & ks) == 0);
            if ((x > y) == up) { key[i] = y; key[p] = x; }
        }
        __syncthreads();
        a = key[eA]; c = key[eB];
        cswap(a, c, ((eA & ks) == 0));
        #pragma unroll
        for (unsigned j = 16; j >= 1; j >>= 1) {
            a = shfl_stage(a, eA, j, ks);
            c = shfl_stage(c, eB, j, ks);
        }
        key[eA] = a; key[eB] = c;
    }
    __syncthreads();

    // ---- write sorted arrays; keep sorted labels in smem ----
    for (int r = tid; r < K_TOT; r += 1024) {
        const ull kk = key[r];
        const int   e  = (int)(kk & 0xffffffffu);
        const float sc = __uint_as_float(~(unsigned)(kk >> 32));
        const int m = e >> 9, n = e & (N_BOX - 1);
        const size_t src = ((size_t)m * B_IMG + b) * N_BOX + n;
        const size_t dst = (size_t)b * K_TOT + r;
        *(float4*)&g_sbox[dst * 4] = *(const float4*)&boxes[src * 4];
        g_sscore[dst] = sc;
        slab[r] = (short)labels[src];
    }
    __syncthreads();

    // ---- per-class stable compaction (warp l handles class l) ----
    if (warp < NUM_CLS) {
        int cnt = 0;
        for (int base = 0; base < K_TOT; base += 32) {
            const bool m = (slab[base + lane] == (short)warp);
            cnt += __popc(__ballot_sync(0xffffffffu, m));
        }
        if (lane == 0) scount[warp] = cnt;
    }
    __syncthreads();
    if (tid == 0) {
        int acc = 0;
        #pragma unroll
        for (int l = 0; l < NUM_CLS; l++) { soff[l] = acc; acc += scount[l]; }
    }
    __syncthreads();
    if (warp < NUM_CLS) {
        const int off = soff[warp];
        int cnt = 0;
        for (int base = 0; base < K_TOT; base += 32) {
            const bool m = (slab[base + lane] == (short)warp);
            const unsigned bal = __ballot_sync(0xffffffffu, m);
            if (m) {
                const int pos = cnt + __popc(bal & ((1u << lane) - 1u));
                g_bidx[b * K_TOT + off + pos] = base + lane;
            }
            cnt += __popc(bal);
        }
        if (lane == 0) {
            g_boff[b * NUM_CLS + warp] = off;
            g_bcnt[b * NUM_CLS + warp] = cnt;
        }
    }
}

// =============================================================================
// K2: per-(image,class) NMS. One block per bucket: load bucket boxes to smem,
// build the tiny upper-triangle suppression matrix (4 warps), run the greedy
// bit-chase in warp 0, and write this bucket's output rows directly.
// Buckets partition all ranks, so the whole (B,K,5) output is covered.
// =============================================================================
__global__ __launch_bounds__(128)
void k_nms(float* __restrict__ out) {
    __shared__ float4 bx[CAP];
    __shared__ float  ar[CAP];
    __shared__ short  srank[CAP];
    __shared__ ull    smask[CAP * W_MAX];      // 8 KB
    __shared__ ull    keepw[W_MAX];
    __shared__ short  kidx[K_TOT];             // fallback kept-rank list (3 KB)

    const int img  = blockIdx.x / NUM_CLS;
    const int cls  = blockIdx.x % NUM_CLS;
    const int tid  = threadIdx.x;
    const int warp = tid >> 5, lane = tid & 31;

    const int off = g_boff[img * NUM_CLS + cls];
    const int cnt = g_bcnt[img * NUM_CLS + cls];
    if (cnt == 0) return;

    if (cnt <= CAP) {
        // ---- gather bucket ----
        for (int m = tid; m < cnt; m += 128) {
            const int rank = g_bidx[img * K_TOT + off + m];
            const float4 bb = *(const float4*)&g_sbox[((size_t)img * K_TOT + rank) * 4];
            bx[m]    = bb;
            ar[m]    = (bb.z - bb.x) * (bb.w - bb.y);
            srank[m] = (short)rank;
        }
        __syncthreads();

        const int W = (cnt + 63) >> 6;
        // ---- suppression matrix, rows striped over 4 warps ----
        for (int r = warp; r < cnt; r += 4) {
            const float4 bi = bx[r];
            const float  ai = ar[r];
            for (int w = r >> 6; w < W; w++) {
                const int j0 = w * 64 + lane;
                const int j1 = j0 + 32;
                bool p0 = false, p1 = false;
                if (j0 > r && j0 < cnt) p0 = iou_gt(bi, ai, bx[j0], ar[j0]);
                if (j1 > r && j1 < cnt) p1 = iou_gt(bi, ai, bx[j1], ar[j1]);
                const unsigned lo = __ballot_sync(0xffffffffu, p0);
                const unsigned hi = __ballot_sync(0xffffffffu, p1);
                if (lane == 0)
                    smask[r * W_MAX + w] = ((ull)hi << 32) | lo;
            }
        }
        __syncthreads();

        // ---- greedy bit-chase (warp 0); words < i>>6 are never written
        //      and are genuinely zero, so guard lane >= i>>6 ----
        if (tid < 32) {
            ull removed = 0ull;
            for (int i = 0; i < cnt; i++) {
                const int c = i >> 6;
                const ull wc = __shfl_sync(0xffffffffu, removed, c);
                if (!((wc >> (i & 63)) & 1ull)) {
                    if (lane >= c && lane < W)
                        removed |= smask[i * W_MAX + lane];
                }
            }
            if (lane < W_MAX) keepw[lane] = (lane < W) ? ~removed : ~0ull;
        }
        __syncthreads();

        // ---- output this bucket's rows ----
        for (int m = tid; m < cnt; m += 128) {
            const bool kp = (keepw[m >> 6] >> (m & 63)) & 1ull;
            const float f = kp ? 1.0f : 0.0f;
            const int rank = srank[m];
            const size_t s = (size_t)img * K_TOT + rank;
            const size_t o = s * 5;
            const float4 bb = bx[m];
            out[o + 0] = bb.x * f;
            out[o + 1] = bb.y * f;
            out[o + 2] = bb.z * f;
            out[o + 3] = bb.w * f;
            out[o + 4] = g_sscore[s] * f;
        }
    } else {
        // ---- fallback (cnt > CAP): warp-sequential kept-list, fully correct ----
        if (warp == 0) {
            int nk = 0;
            for (int c = 0; c < cnt; c++) {
                const int rank = g_bidx[img * K_TOT + off + c];
                const size_t s = (size_t)img * K_TOT + rank;
                const float4 bc = *(const float4*)&g_sbox[s * 4];
                const float  ac = (bc.z - bc.x) * (bc.w - bc.y);
                bool sup = false;
                for (int k = lane; k < nk; k += 32) {
                    const int rk = kidx[k];
                    const float4 bk = *(const float4*)&g_sbox[((size_t)img * K_TOT + rk) * 4];
                    const float  ak = (bk.z - bk.x) * (bk.w - bk.y);
                    if (iou_gt(bc, ac, bk, ak)) { sup = true; break; }
                }
                sup = (__ballot_sync(0xffffffffu, sup) != 0u);
                if (!sup) {
                    if (lane == 0) kidx[nk] = (short)rank;
                    nk++;
                }
                if (lane == 0) {
                    const float f = sup ? 0.0f : 1.0f;
                    const size_t o = s * 5;
                    out[o + 0] = bc.x * f;
                    out[o + 1] = bc.y * f;
                    out[o + 2] = bc.z * f;
                    out[o + 3] = bc.w * f;
                    out[o + 4] = g_sscore[s] * f;
                }
                __syncwarp();
            }
        }
    }
}

// =============================================================================
extern "C" void kernel_launch(void* const* d_in, const int* in_sizes, int n_in,
                              void* d_out, int out_size) {
    const float* boxes   = (const float*)d_in[0];
    const float* scores  = (const float*)d_in[1];
    const int*   labels  = (const int*)  d_in[2];
    const float* weights = (const float*)d_in[3];
    float*       out     = (float*)d_out;

    k_sort<<<B_IMG, 1024>>>(boxes, scores, labels, weights);
    k_nms <<<B_IMG * NUM_CLS, 128>>>(out);
}